// round 3
// baseline (speedup 1.0000x reference)
#include <cuda_runtime.h>
#include <cuda_bf16.h>
#include <math.h>

// Problem constants
#define BB 2
#define TT 4096
#define DD 2048
#define NHEAD 8
#define HD 256
#define TOK (BB*TT)           // 8192

// ---------------- scratch (device globals; no allocation allowed) ----------
__device__ float g_Q[(size_t)TOK * NHEAD * HD];   // 64 MiB
__device__ float g_K[(size_t)TOK * HD];           // 8 MiB
__device__ float g_V[(size_t)TOK * HD];           // 8 MiB
__device__ float g_enc[(size_t)TOK * NHEAD * HD]; // 64 MiB

// ===========================================================================
// Kernel 1: fused QKV projection.
// C[token, j] for j in [0,2560): j<2048 -> Q head j/256, col j%256
//                               j in [2048,2304) -> K, j in [2304,2560) -> V
// All weight slabs are [D][H] row-major with d-stride H, so one SGEMM with a
// per-tile base pointer works.  Tiles: 128x128x16, 256 threads, 8x8 micro.
// ===========================================================================
__global__ __launch_bounds__(256) void proj_qkv_kernel(
    const float* __restrict__ x,
    const float* __restrict__ qw,
    const float* __restrict__ kvw)
{
    __shared__ float As[16][132];
    __shared__ float Bs[16][132];

    const int tid = threadIdx.x;
    const int tx = tid & 15, ty = tid >> 4;
    const int j0 = blockIdx.x * 128;
    const int m0 = blockIdx.y * 128;

    const int g = j0 >> 8;          // weight group 0..9
    const int h0 = j0 & 255;        // col offset inside group (0 or 128)
    const float* bb = (g < 8) ? (qw + (size_t)g * (DD * HD))
                              : (kvw + (size_t)(g - 8) * (DD * HD));

    float acc[8][8];
#pragma unroll
    for (int u = 0; u < 8; ++u)
#pragma unroll
        for (int v = 0; v < 8; ++v) acc[u][v] = 0.f;

    const int bk = tid >> 4;            // 0..15 (B tile k row)
    const int bj = (tid & 15) * 8;      // 0..120 (B tile col)

    for (int k0 = 0; k0 < DD; k0 += 16) {
        __syncthreads();
        // A tile: 128 rows x 16 k, stored transposed As[k][m]
#pragma unroll
        for (int u = 0; u < 2; ++u) {
            int v = tid + u * 256;          // float4 id 0..511
            int r = v >> 2;
            int kq = (v & 3) * 4;
            float4 a = *(const float4*)&x[(size_t)(m0 + r) * DD + k0 + kq];
            As[kq + 0][r] = a.x;
            As[kq + 1][r] = a.y;
            As[kq + 2][r] = a.z;
            As[kq + 3][r] = a.w;
        }
        // B tile: Bs[k][jj]
        {
            const float* src = bb + (size_t)(k0 + bk) * HD + h0 + bj;
            float4 b0 = *(const float4*)(src);
            float4 b1 = *(const float4*)(src + 4);
            *(float4*)&Bs[bk][bj] = b0;
            *(float4*)&Bs[bk][bj + 4] = b1;
        }
        __syncthreads();

#pragma unroll
        for (int k = 0; k < 16; ++k) {
            float a[8], bvals[8];
            *(float4*)&a[0] = *(const float4*)&As[k][ty * 8];
            *(float4*)&a[4] = *(const float4*)&As[k][ty * 8 + 4];
            *(float4*)&bvals[0] = *(const float4*)&Bs[k][tx * 8];
            *(float4*)&bvals[4] = *(const float4*)&Bs[k][tx * 8 + 4];
#pragma unroll
            for (int u = 0; u < 8; ++u)
#pragma unroll
                for (int v = 0; v < 8; ++v)
                    acc[u][v] += a[u] * bvals[v];
        }
    }

    // Epilogue: route to g_Q / g_K / g_V
    float* dst;
    int stride, colbase;
    if (j0 < 2048)      { dst = g_Q; stride = NHEAD * HD; colbase = j0; }
    else if (j0 < 2304) { dst = g_K; stride = HD;        colbase = j0 - 2048; }
    else                { dst = g_V; stride = HD;        colbase = j0 - 2304; }

#pragma unroll
    for (int u = 0; u < 8; ++u) {
        size_t row = (size_t)(m0 + ty * 8 + u);
        float4 v0 = make_float4(acc[u][0], acc[u][1], acc[u][2], acc[u][3]);
        float4 v1 = make_float4(acc[u][4], acc[u][5], acc[u][6], acc[u][7]);
        *(float4*)&dst[row * stride + colbase + tx * 8]     = v0;
        *(float4*)&dst[row * stride + colbase + tx * 8 + 4] = v1;
    }
}

// ===========================================================================
// Kernel 2: RoPE (+ query scale).  blockIdx.x = token, blockIdx.y = head
// (0..7 = Q heads, 8 = K).  threadIdx.x = i in [0,128).
// Double-precision angle to stay well inside the reference's fp32 envelope.
// ===========================================================================
__global__ void rope_kernel()
{
    const int tok = blockIdx.x;
    const int head = blockIdx.y;
    const int i = threadIdx.x;
    const int t = tok & (TT - 1);

    double inv = pow(10000.0, -(double)i / 128.0);
    double ang = (double)t * inv;
    float s = (float)sin(ang);
    float c = (float)cos(ang);

    float* p;
    float scale;
    if (head < NHEAD) {
        p = g_Q + (size_t)tok * (NHEAD * HD) + head * HD;
        scale = 0.0625f;   // H^-0.5 = 1/16
    } else {
        p = g_K + (size_t)tok * HD;
        scale = 1.0f;
    }
    float a = p[i];
    float bq = p[i + 128];
    p[i]       = (a * c - bq * s) * scale;
    p[i + 128] = (bq * c + a * s) * scale;
}

// ===========================================================================
// Kernel 3: causal flash attention.
// BLOCK_M = BLOCK_N = 64, head dim 256 fully resident in smem (fp32).
// 256 threads (tx 0..15, ty 0..15).  Fragments are interleaved (stride 16)
// to keep shared-memory bank conflicts <= 2-way.
// Thread owns S rows ty+16i / cols tx+16j (4x4), O rows ty+16i / cols
// tx*16..tx*16+15 (4x16).
// ===========================================================================
#define QSTR 260   // padded row stride (floats), multiple of 4
#define PSTR 65
#define FLASH_SMEM_FLOATS (3 * 64 * QSTR + 64 * PSTR)
#define FLASH_SMEM_BYTES  (FLASH_SMEM_FLOATS * 4)

__global__ __launch_bounds__(256) void flash_kernel()
{
    extern __shared__ float sm[];
    float* Qs = sm;
    float* Ks = sm + 64 * QSTR;
    float* Vs = sm + 2 * 64 * QSTR;
    float* Ps = sm + 3 * 64 * QSTR;

    const int tid = threadIdx.x;
    const int tx = tid & 15, ty = tid >> 4;
    // heavy (late) query tiles first to avoid tail imbalance
    const int bx = gridDim.x - 1 - blockIdx.x;
    const int n = blockIdx.y;
    const int b = blockIdx.z;
    const int q0 = bx * 64;
    const size_t tb = (size_t)b * TT;

    // Load Q tile (64 x 256)
    for (int idx = tid; idx < 64 * 64; idx += 256) {
        int r = idx >> 6;
        int c4 = (idx & 63) * 4;
        *(float4*)&Qs[r * QSTR + c4] =
            *(const float4*)&g_Q[((tb + q0 + r) * NHEAD + n) * HD + c4];
    }

    float o[4][16];
#pragma unroll
    for (int i = 0; i < 4; ++i)
#pragma unroll
        for (int j = 0; j < 16; ++j) o[i][j] = 0.f;
    float m[4] = {-1e30f, -1e30f, -1e30f, -1e30f};
    float l[4] = {0.f, 0.f, 0.f, 0.f};

    const int ntiles = bx + 1;
    for (int kt = 0; kt < ntiles; ++kt) {
        const int s0 = kt * 64;
        __syncthreads();   // previous iter's Ps/Vs reads done; Qs visible (1st iter)
        for (int idx = tid; idx < 64 * 64; idx += 256) {
            int r = idx >> 6;
            int c4 = (idx & 63) * 4;
            *(float4*)&Ks[r * QSTR + c4] =
                *(const float4*)&g_K[(tb + s0 + r) * HD + c4];
            *(float4*)&Vs[r * QSTR + c4] =
                *(const float4*)&g_V[(tb + s0 + r) * HD + c4];
        }
        __syncthreads();

        // S = Q K^T  (4x4 fragment per thread)
        float s[4][4];
#pragma unroll
        for (int i = 0; i < 4; ++i)
#pragma unroll
            for (int j = 0; j < 4; ++j) s[i][j] = 0.f;

#pragma unroll 2
        for (int k = 0; k < 256; k += 4) {
            float4 qf[4], kf[4];
#pragma unroll
            for (int i = 0; i < 4; ++i)
                qf[i] = *(const float4*)&Qs[(ty + 16 * i) * QSTR + k];
#pragma unroll
            for (int j = 0; j < 4; ++j)
                kf[j] = *(const float4*)&Ks[(tx + 16 * j) * QSTR + k];
#pragma unroll
            for (int i = 0; i < 4; ++i)
#pragma unroll
                for (int j = 0; j < 4; ++j)
                    s[i][j] += qf[i].x * kf[j].x + qf[i].y * kf[j].y
                             + qf[i].z * kf[j].z + qf[i].w * kf[j].w;
        }

        // causal mask only on the diagonal tile
        if (kt == bx) {
#pragma unroll
            for (int i = 0; i < 4; ++i)
#pragma unroll
                for (int j = 0; j < 4; ++j)
                    if (tx + 16 * j > ty + 16 * i) s[i][j] = -1e30f;
        }

        // online softmax update
#pragma unroll
        for (int i = 0; i < 4; ++i) {
            float mt = fmaxf(fmaxf(s[i][0], s[i][1]), fmaxf(s[i][2], s[i][3]));
#pragma unroll
            for (int off = 1; off < 16; off <<= 1)
                mt = fmaxf(mt, __shfl_xor_sync(0xffffffffu, mt, off));
            float mn = fmaxf(m[i], mt);
            float alpha = __expf(m[i] - mn);
            float ls = 0.f;
#pragma unroll
            for (int j = 0; j < 4; ++j) {
                float p = __expf(s[i][j] - mn);
                s[i][j] = p;
                ls += p;
            }
#pragma unroll
            for (int off = 1; off < 16; off <<= 1)
                ls += __shfl_xor_sync(0xffffffffu, ls, off);
            l[i] = l[i] * alpha + ls;
            m[i] = mn;
#pragma unroll
            for (int j = 0; j < 16; ++j) o[i][j] *= alpha;
#pragma unroll
            for (int j = 0; j < 4; ++j)
                Ps[(ty + 16 * i) * PSTR + tx + 16 * j] = s[i][j];
        }
        __syncthreads();

        // O += P V   (rows ty+16i, cols tx*16..+15)
#pragma unroll 2
        for (int ss = 0; ss < 64; ++ss) {
            float p[4];
#pragma unroll
            for (int i = 0; i < 4; ++i)
                p[i] = Ps[(ty + 16 * i) * PSTR + ss];
            float4 v[4];
#pragma unroll
            for (int j = 0; j < 4; ++j)
                v[j] = *(const float4*)&Vs[ss * QSTR + tx * 16 + 4 * j];
#pragma unroll
            for (int i = 0; i < 4; ++i) {
#pragma unroll
                for (int j = 0; j < 4; ++j) {
                    o[i][4 * j + 0] += p[i] * v[j].x;
                    o[i][4 * j + 1] += p[i] * v[j].y;
                    o[i][4 * j + 2] += p[i] * v[j].z;
                    o[i][4 * j + 3] += p[i] * v[j].w;
                }
            }
        }
    }

    // epilogue: normalize and write encoded
#pragma unroll
    for (int i = 0; i < 4; ++i) {
        float inv = 1.f / l[i];
        size_t row = tb + q0 + ty + 16 * i;
#pragma unroll
        for (int j = 0; j < 4; ++j) {
            float4 v = make_float4(o[i][4 * j + 0] * inv, o[i][4 * j + 1] * inv,
                                   o[i][4 * j + 2] * inv, o[i][4 * j + 3] * inv);
            *(float4*)&g_enc[(row * NHEAD + n) * HD + tx * 16 + 4 * j] = v;
        }
    }
}

// ===========================================================================
// Kernel 4: output projection.  out[token, d] = enc[token, nh] * W[nh, d]
// enc layout [token][n*256+h] matches out_w flattened [n*H+h][d] row-major.
// ===========================================================================
__global__ __launch_bounds__(256) void proj_out_kernel(
    const float* __restrict__ ow,
    float* __restrict__ out)
{
    __shared__ float As[16][132];
    __shared__ float Bs[16][132];

    const int tid = threadIdx.x;
    const int tx = tid & 15, ty = tid >> 4;
    const int j0 = blockIdx.x * 128;
    const int m0 = blockIdx.y * 128;

    float acc[8][8];
#pragma unroll
    for (int u = 0; u < 8; ++u)
#pragma unroll
        for (int v = 0; v < 8; ++v) acc[u][v] = 0.f;

    const int bk = tid >> 4;
    const int bj = (tid & 15) * 8;

    for (int k0 = 0; k0 < DD; k0 += 16) {
        __syncthreads();
#pragma unroll
        for (int u = 0; u < 2; ++u) {
            int v = tid + u * 256;
            int r = v >> 2;
            int kq = (v & 3) * 4;
            float4 a = *(const float4*)&g_enc[(size_t)(m0 + r) * DD + k0 + kq];
            As[kq + 0][r] = a.x;
            As[kq + 1][r] = a.y;
            As[kq + 2][r] = a.z;
            As[kq + 3][r] = a.w;
        }
        {
            const float* src = ow + (size_t)(k0 + bk) * DD + j0 + bj;
            float4 b0 = *(const float4*)(src);
            float4 b1 = *(const float4*)(src + 4);
            *(float4*)&Bs[bk][bj] = b0;
            *(float4*)&Bs[bk][bj + 4] = b1;
        }
        __syncthreads();

#pragma unroll
        for (int k = 0; k < 16; ++k) {
            float a[8], bvals[8];
            *(float4*)&a[0] = *(const float4*)&As[k][ty * 8];
            *(float4*)&a[4] = *(const float4*)&As[k][ty * 8 + 4];
            *(float4*)&bvals[0] = *(const float4*)&Bs[k][tx * 8];
            *(float4*)&bvals[4] = *(const float4*)&Bs[k][tx * 8 + 4];
#pragma unroll
            for (int u = 0; u < 8; ++u)
#pragma unroll
                for (int v = 0; v < 8; ++v)
                    acc[u][v] += a[u] * bvals[v];
        }
    }

#pragma unroll
    for (int u = 0; u < 8; ++u) {
        size_t row = (size_t)(m0 + ty * 8 + u);
        float4 v0 = make_float4(acc[u][0], acc[u][1], acc[u][2], acc[u][3]);
        float4 v1 = make_float4(acc[u][4], acc[u][5], acc[u][6], acc[u][7]);
        *(float4*)&out[row * DD + j0 + tx * 8]     = v0;
        *(float4*)&out[row * DD + j0 + tx * 8 + 4] = v1;
    }
}

// ===========================================================================
// launch
// inputs (metadata order): 0=x, 1=segment_pos, 2=attn_mask, 3=q_w, 4=kv_w, 5=out_w
// segment_pos is arange(T) and attn_mask is causal tril -> both implicit.
// ===========================================================================
extern "C" void kernel_launch(void* const* d_in, const int* in_sizes, int n_in,
                              void* d_out, int out_size)
{
    (void)in_sizes; (void)n_in; (void)out_size;
    const float* x   = (const float*)d_in[0];
    const float* qw  = (const float*)d_in[3];
    const float* kvw = (const float*)d_in[4];
    const float* ow  = (const float*)d_in[5];
    float* out = (float*)d_out;

    proj_qkv_kernel<<<dim3(20, 64), 256>>>(x, qw, kvw);
    rope_kernel<<<dim3(TOK, NHEAD + 1), 128>>>();

    cudaFuncSetAttribute(flash_kernel,
                         cudaFuncAttributeMaxDynamicSharedMemorySize,
                         FLASH_SMEM_BYTES);
    flash_kernel<<<dim3(TT / 64, NHEAD, BB), 256, FLASH_SMEM_BYTES>>>();

    proj_out_kernel<<<dim3(16, 64), 256>>>(ow, out);
}

// round 6
// speedup vs baseline: 1.2277x; 1.2277x over previous
#include <cuda_runtime.h>
#include <cuda_bf16.h>
#include <math.h>
#include <stdint.h>

// Problem constants
#define BB 2
#define TT 4096
#define DD 2048
#define NHEAD 8
#define HD 256
#define TOK (BB*TT)           // 8192
#define NQKV 2560             // 8*256 Q + 256 K + 256 V

// ---------------- scratch (device globals; no allocation allowed) ----------
__device__ float g_Q[(size_t)TOK * NHEAD * HD];   // 64 MiB
__device__ float g_K[(size_t)TOK * HD];           // 8 MiB
__device__ float g_V[(size_t)TOK * HD];           // 8 MiB
__device__ float g_enc[(size_t)TOK * NHEAD * HD]; // 64 MiB
// split-bf16 operands for HMMA GEMMs (A = activations, B = weights K-major)
__device__ __nv_bfloat16 g_Ahi[(size_t)TOK * DD];   // 32 MiB
__device__ __nv_bfloat16 g_Alo[(size_t)TOK * DD];   // 32 MiB
__device__ __nv_bfloat16 g_Bhi[(size_t)NQKV * DD];  // 10 MiB
__device__ __nv_bfloat16 g_Blo[(size_t)NQKV * DD];  // 10 MiB

// =================== ptx helpers ========================
__device__ __forceinline__ uint32_t s2u(const void* p) {
    uint32_t a;
    asm("{ .reg .u64 t; cvta.to.shared.u64 t, %1; cvt.u32.u64 %0, t; }"
        : "=r"(a) : "l"(p));
    return a;
}
__device__ __forceinline__ void cpa16(uint32_t s, const void* g) {
    asm volatile("cp.async.cg.shared.global [%0], [%1], 16;" :: "r"(s), "l"(g));
}
#define CP_COMMIT()  asm volatile("cp.async.commit_group;" ::: "memory")
#define CP_WAIT(N)   asm volatile("cp.async.wait_group %0;" :: "n"(N) : "memory")

#define LDSM4(r0, r1, r2, r3, addr) \
    asm volatile("ldmatrix.sync.aligned.m8n8.x4.shared.b16 {%0,%1,%2,%3}, [%4];" \
                 : "=r"(r0), "=r"(r1), "=r"(r2), "=r"(r3) : "r"(addr))

#define MMA16816(d, a, b0, b1) \
    asm volatile("mma.sync.aligned.m16n8k16.row.col.f32.bf16.bf16.f32 " \
                 "{%0,%1,%2,%3}, {%4,%5,%6,%7}, {%8,%9}, {%0,%1,%2,%3};" \
                 : "+f"((d)[0]), "+f"((d)[1]), "+f"((d)[2]), "+f"((d)[3]) \
                 : "r"((a)[0]), "r"((a)[1]), "r"((a)[2]), "r"((a)[3]), \
                   "r"(b0), "r"(b1))

// ===========================================================================
// Prep 1: transpose+split qkv weights into g_Bhi/g_Blo  ([N=2560][K=2048])
// group g in [0,10): 0..7 = q heads, 8 = K, 9 = V; slab [2048][256]
// ===========================================================================
__global__ void transpose_qkvw(const float* __restrict__ qw,
                               const float* __restrict__ kvw) {
    __shared__ float t[32][33];
    const int g = blockIdx.z;
    const float* slab = (g < 8) ? qw + (size_t)g * DD * HD
                                : kvw + (size_t)(g - 8) * DD * HD;
    const int h0 = blockIdx.x * 32, k0 = blockIdx.y * 32;
    const int c = threadIdx.x, r0 = threadIdx.y;   // (32,8)
#pragma unroll
    for (int i = 0; i < 32; i += 8)
        t[r0 + i][c] = slab[(size_t)(k0 + r0 + i) * HD + h0 + c];
    __syncthreads();
#pragma unroll
    for (int i = 0; i < 32; i += 8) {
        float v = t[c][r0 + i];
        size_t o = (size_t)(g * 256 + h0 + r0 + i) * DD + k0 + c;
        __nv_bfloat16 hi = __float2bfloat16(v);
        g_Bhi[o] = hi;
        g_Blo[o] = __float2bfloat16(v - __bfloat162float(hi));
    }
}

// Prep 2: transpose+split out_w ([k=nh 2048][d 2048]) -> g_Bhi/lo [d][nh]
__global__ void transpose_outw(const float* __restrict__ ow) {
    __shared__ float t[32][33];
    const int j0 = blockIdx.x * 32, k0 = blockIdx.y * 32;
    const int c = threadIdx.x, r0 = threadIdx.y;
#pragma unroll
    for (int i = 0; i < 32; i += 8)
        t[r0 + i][c] = ow[(size_t)(k0 + r0 + i) * DD + j0 + c];
    __syncthreads();
#pragma unroll
    for (int i = 0; i < 32; i += 8) {
        float v = t[c][r0 + i];
        size_t o = (size_t)(j0 + r0 + i) * DD + k0 + c;
        __nv_bfloat16 hi = __float2bfloat16(v);
        g_Bhi[o] = hi;
        g_Blo[o] = __float2bfloat16(v - __bfloat162float(hi));
    }
}

// Prep 3: split activations (x or g_enc) into g_Ahi/g_Alo
__global__ void convert_split(const float* __restrict__ src, int use_enc) {
    const float* p = use_enc ? (const float*)g_enc : src;
    size_t i = (size_t)blockIdx.x * blockDim.x + threadIdx.x;   // float4 index
    float4 v = ((const float4*)p)[i];
    __nv_bfloat16 hx = __float2bfloat16(v.x), hy = __float2bfloat16(v.y);
    __nv_bfloat16 hz = __float2bfloat16(v.z), hw = __float2bfloat16(v.w);
    __nv_bfloat162* h2 = (__nv_bfloat162*)g_Ahi;
    __nv_bfloat162* l2 = (__nv_bfloat162*)g_Alo;
    h2[2 * i]     = __halves2bfloat162(hx, hy);
    h2[2 * i + 1] = __halves2bfloat162(hz, hw);
    l2[2 * i]     = __halves2bfloat162(
        __float2bfloat16(v.x - __bfloat162float(hx)),
        __float2bfloat16(v.y - __bfloat162float(hy)));
    l2[2 * i + 1] = __halves2bfloat162(
        __float2bfloat16(v.z - __bfloat162float(hz)),
        __float2bfloat16(v.w - __bfloat162float(hw)));
}

// ===========================================================================
// HMMA 3xBF16 GEMM: C[M=8192, N][K=2048], CTA tile 128x128, K-chunk 32,
// double-buffered cp.async.  8 warps, warp tile 64(m) x 32(n), fragments
// m16n8k16.  D = Ahi*Bhi + Ahi*Blo + Alo*Bhi accumulated in fp32.
// mode 0: epilogue routes to g_Q/g_K/g_V (qkv);  mode 1: plain -> outp.
// smem per stage: 4 tiles x 128 rows x 40 bf16 (80B padded rows).
// ===========================================================================
#define KC 32
#define TROW 80                 // bytes per padded row (32 bf16 data + pad)
#define TILEB (128 * TROW)      // 10240 B
#define STAGEB (4 * TILEB)      // 40960 B
#define GSM_TOTAL (2 * STAGEB)  // 81920 B

__device__ __forceinline__ void load_stage(uint32_t smb, int s, int k0, int tid,
                                           const __nv_bfloat16* const* base) {
    uint32_t sb = smb + s * STAGEB;
#pragma unroll
    for (int j = 0; j < 8; ++j) {
        int c = tid + j * 256;            // chunk 0..2047
        const int tile = j >> 1;          // 512 chunks per tile, 2 j's per tile
        int inner = c & 511;
        int row = inner >> 2, seg = inner & 3;
        const __nv_bfloat16* gp = base[tile] + (size_t)row * DD + k0 + seg * 8;
        cpa16(sb + tile * TILEB + row * TROW + seg * 16, gp);
    }
    CP_COMMIT();
}

__global__ __launch_bounds__(256, 1) void gemm3x_kernel(float* outp, int mode) {
    extern __shared__ __align__(128) char sm[];
    uint32_t smb = s2u(sm);
    const int tid = threadIdx.x;
    const int lane = tid & 31, wid = tid >> 5;
    const int wm = wid & 1, wn = wid >> 1;     // 2 x 4 warp grid
    const int n0 = blockIdx.x * 128;
    const int m0 = blockIdx.y * 128;

    const __nv_bfloat16* base[4] = {
        g_Ahi + (size_t)m0 * DD, g_Alo + (size_t)m0 * DD,
        g_Bhi + (size_t)n0 * DD, g_Blo + (size_t)n0 * DD };

    float acc[4][4][4];
#pragma unroll
    for (int i = 0; i < 4; ++i)
#pragma unroll
        for (int j = 0; j < 4; ++j)
#pragma unroll
            for (int r = 0; r < 4; ++r) acc[i][j][r] = 0.f;

    // ldmatrix lane-address offsets (stage-relative)
    // A: row = wm*64 + mf*16 + (lane&15), 16B half = lane>>4
    const uint32_t a_off = (uint32_t)((wm * 64 + (lane & 15)) * TROW
                                      + (lane >> 4) * 16);
    // B: row = wn*32 + pair*16 + (lane>>4)*8 + (lane&7), 16B half = (lane>>3)&1
    const uint32_t b_off = (uint32_t)((wn * 32 + (lane >> 4) * 8 + (lane & 7)) * TROW
                                      + ((lane >> 3) & 1) * 16);

    load_stage(smb, 0, 0, tid, base);

    const int NIT = DD / KC;   // 64
    for (int it = 0; it < NIT; ++it) {
        const int s = it & 1;
        if (it + 1 < NIT) {
            load_stage(smb, s ^ 1, (it + 1) * KC, tid, base);
            CP_WAIT(1);
        } else {
            CP_WAIT(0);
        }
        __syncthreads();

        const uint32_t st = smb + s * STAGEB;
#pragma unroll
        for (int ks = 0; ks < 2; ++ks) {
            const uint32_t ko = ks * 32;   // 16 bf16 = 32B per k-step
            uint32_t ahi[4][4], alo[4][4];
#pragma unroll
            for (int mf = 0; mf < 4; ++mf) {
                uint32_t aa = st + a_off + mf * (16 * TROW) + ko;
                LDSM4(ahi[mf][0], ahi[mf][1], ahi[mf][2], ahi[mf][3], aa);
                LDSM4(alo[mf][0], alo[mf][1], alo[mf][2], alo[mf][3], aa + TILEB);
            }
            uint32_t bhi[4][2], blo[4][2];
#pragma unroll
            for (int pr = 0; pr < 2; ++pr) {
                uint32_t ba = st + 2 * TILEB + b_off + pr * (16 * TROW) + ko;
                LDSM4(bhi[2 * pr][0], bhi[2 * pr][1],
                      bhi[2 * pr + 1][0], bhi[2 * pr + 1][1], ba);
                LDSM4(blo[2 * pr][0], blo[2 * pr][1],
                      blo[2 * pr + 1][0], blo[2 * pr + 1][1], ba + TILEB);
            }
#pragma unroll
            for (int mf = 0; mf < 4; ++mf)
#pragma unroll
                for (int nf = 0; nf < 4; ++nf) {
                    MMA16816(acc[mf][nf], ahi[mf], bhi[nf][0], bhi[nf][1]);
                    MMA16816(acc[mf][nf], ahi[mf], blo[nf][0], blo[nf][1]);
                    MMA16816(acc[mf][nf], alo[mf], bhi[nf][0], bhi[nf][1]);
                }
        }
        __syncthreads();
    }

    // Epilogue: c-frag (m16n8): rows lane>>2 (+8), cols 2*(lane&3)(+1)
    float* dst; int stride, colbase;
    if (mode == 0) {
        if (n0 < 2048)      { dst = g_Q; stride = NHEAD * HD; colbase = n0; }
        else if (n0 < 2304) { dst = g_K; stride = HD; colbase = n0 - 2048; }
        else                { dst = g_V; stride = HD; colbase = n0 - 2304; }
    } else { dst = outp; stride = DD; colbase = n0; }

    const int r0 = m0 + wm * 64 + (lane >> 2);
    const int c0 = colbase + wn * 32 + 2 * (lane & 3);
#pragma unroll
    for (int mf = 0; mf < 4; ++mf)
#pragma unroll
        for (int nf = 0; nf < 4; ++nf) {
            float* p0 = dst + (size_t)(r0 + mf * 16) * stride + c0 + nf * 8;
            *(float2*)p0 = make_float2(acc[mf][nf][0], acc[mf][nf][1]);
            float* p1 = p0 + 8 * stride;
            *(float2*)p1 = make_float2(acc[mf][nf][2], acc[mf][nf][3]);
        }
}

// ===========================================================================
// RoPE (+ query scale)
// ===========================================================================
__global__ void rope_kernel() {
    const int tok = blockIdx.x;
    const int head = blockIdx.y;
    const int i = threadIdx.x;
    const int t = tok & (TT - 1);

    double inv = pow(10000.0, -(double)i / 128.0);
    double ang = (double)t * inv;
    float s = (float)sin(ang);
    float c = (float)cos(ang);

    float* p;
    float scale;
    if (head < NHEAD) {
        p = g_Q + (size_t)tok * (NHEAD * HD) + head * HD;
        scale = 0.0625f;
    } else {
        p = g_K + (size_t)tok * HD;
        scale = 1.0f;
    }
    float a = p[i];
    float bq = p[i + 128];
    p[i]       = (a * c - bq * s) * scale;
    p[i + 128] = (bq * c + a * s) * scale;
}

// ===========================================================================
// Causal flash attention — unchanged this round (next: HMMA)
// ===========================================================================
#define QSTR 260
#define PSTR 65
#define FLASH_SMEM_FLOATS (3 * 64 * QSTR + 64 * PSTR)
#define FLASH_SMEM_BYTES  (FLASH_SMEM_FLOATS * 4)

__global__ __launch_bounds__(256) void flash_kernel() {
    extern __shared__ float smf[];
    float* Qs = smf;
    float* Ks = smf + 64 * QSTR;
    float* Vs = smf + 2 * 64 * QSTR;
    float* Ps = smf + 3 * 64 * QSTR;

    const int tid = threadIdx.x;
    const int tx = tid & 15, ty = tid >> 4;
    const int bx = gridDim.x - 1 - blockIdx.x;
    const int n = blockIdx.y;
    const int b = blockIdx.z;
    const int q0 = bx * 64;
    const size_t tb = (size_t)b * TT;

    for (int idx = tid; idx < 64 * 64; idx += 256) {
        int r = idx >> 6;
        int c4 = (idx & 63) * 4;
        *(float4*)&Qs[r * QSTR + c4] =
            *(const float4*)&g_Q[((tb + q0 + r) * NHEAD + n) * HD + c4];
    }

    float o[4][16];
#pragma unroll
    for (int i = 0; i < 4; ++i)
#pragma unroll
        for (int j = 0; j < 16; ++j) o[i][j] = 0.f;
    float m[4] = {-1e30f, -1e30f, -1e30f, -1e30f};
    float l[4] = {0.f, 0.f, 0.f, 0.f};

    const int ntiles = bx + 1;
    for (int kt = 0; kt < ntiles; ++kt) {
        const int s0 = kt * 64;
        __syncthreads();
        for (int idx = tid; idx < 64 * 64; idx += 256) {
            int r = idx >> 6;
            int c4 = (idx & 63) * 4;
            *(float4*)&Ks[r * QSTR + c4] =
                *(const float4*)&g_K[(tb + s0 + r) * HD + c4];
            *(float4*)&Vs[r * QSTR + c4] =
                *(const float4*)&g_V[(tb + s0 + r) * HD + c4];
        }
        __syncthreads();

        float s[4][4];
#pragma unroll
        for (int i = 0; i < 4; ++i)
#pragma unroll
            for (int j = 0; j < 4; ++j) s[i][j] = 0.f;

#pragma unroll 2
        for (int k = 0; k < 256; k += 4) {
            float4 qf[4], kf[4];
#pragma unroll
            for (int i = 0; i < 4; ++i)
                qf[i] = *(const float4*)&Qs[(ty + 16 * i) * QSTR + k];
#pragma unroll
            for (int j = 0; j < 4; ++j)
                kf[j] = *(const float4*)&Ks[(tx + 16 * j) * QSTR + k];
#pragma unroll
            for (int i = 0; i < 4; ++i)
#pragma unroll
                for (int j = 0; j < 4; ++j)
                    s[i][j] += qf[i].x * kf[j].x + qf[i].y * kf[j].y
                             + qf[i].z * kf[j].z + qf[i].w * kf[j].w;
        }

        if (kt == bx) {
#pragma unroll
            for (int i = 0; i < 4; ++i)
#pragma unroll
                for (int j = 0; j < 4; ++j)
                    if (tx + 16 * j > ty + 16 * i) s[i][j] = -1e30f;
        }

#pragma unroll
        for (int i = 0; i < 4; ++i) {
            float mt = fmaxf(fmaxf(s[i][0], s[i][1]), fmaxf(s[i][2], s[i][3]));
#pragma unroll
            for (int off = 1; off < 16; off <<= 1)
                mt = fmaxf(mt, __shfl_xor_sync(0xffffffffu, mt, off));
            float mn = fmaxf(m[i], mt);
            float alpha = __expf(m[i] - mn);
            float ls = 0.f;
#pragma unroll
            for (int j = 0; j < 4; ++j) {
                float p = __expf(s[i][j] - mn);
                s[i][j] = p;
                ls += p;
            }
#pragma unroll
            for (int off = 1; off < 16; off <<= 1)
                ls += __shfl_xor_sync(0xffffffffu, ls, off);
            l[i] = l[i] * alpha + ls;
            m[i] = mn;
#pragma unroll
            for (int j = 0; j < 16; ++j) o[i][j] *= alpha;
#pragma unroll
            for (int j = 0; j < 4; ++j)
                Ps[(ty + 16 * i) * PSTR + tx + 16 * j] = s[i][j];
        }
        __syncthreads();

#pragma unroll 2
        for (int ss = 0; ss < 64; ++ss) {
            float p[4];
#pragma unroll
            for (int i = 0; i < 4; ++i)
                p[i] = Ps[(ty + 16 * i) * PSTR + ss];
            float4 v[4];
#pragma unroll
            for (int j = 0; j < 4; ++j)
                v[j] = *(const float4*)&Vs[ss * QSTR + tx * 16 + 4 * j];
#pragma unroll
            for (int i = 0; i < 4; ++i) {
#pragma unroll
                for (int j = 0; j < 4; ++j) {
                    o[i][4 * j + 0] += p[i] * v[j].x;
                    o[i][4 * j + 1] += p[i] * v[j].y;
                    o[i][4 * j + 2] += p[i] * v[j].z;
                    o[i][4 * j + 3] += p[i] * v[j].w;
                }
            }
        }
    }

#pragma unroll
    for (int i = 0; i < 4; ++i) {
        float inv = 1.f / l[i];
        size_t row = tb + q0 + ty + 16 * i;
#pragma unroll
        for (int j = 0; j < 4; ++j) {
            float4 v = make_float4(o[i][4 * j + 0] * inv, o[i][4 * j + 1] * inv,
                                   o[i][4 * j + 2] * inv, o[i][4 * j + 3] * inv);
            *(float4*)&g_enc[(row * NHEAD + n) * HD + tx * 16 + 4 * j] = v;
        }
    }
}

// ===========================================================================
// launch — inputs: 0=x, 1=segment_pos, 2=attn_mask, 3=q_w, 4=kv_w, 5=out_w
// ===========================================================================
extern "C" void kernel_launch(void* const* d_in, const int* in_sizes, int n_in,
                              void* d_out, int out_size) {
    (void)in_sizes; (void)n_in; (void)out_size;
    const float* x   = (const float*)d_in[0];
    const float* qw  = (const float*)d_in[3];
    const float* kvw = (const float*)d_in[4];
    const float* ow  = (const float*)d_in[5];
    float* out = (float*)d_out;

    cudaFuncSetAttribute(gemm3x_kernel,
                         cudaFuncAttributeMaxDynamicSharedMemorySize, GSM_TOTAL);
    cudaFuncSetAttribute(flash_kernel,
                         cudaFuncAttributeMaxDynamicSharedMemorySize,
                         FLASH_SMEM_BYTES);

    // QKV projection on HMMA (3xBF16 split)
    transpose_qkvw<<<dim3(HD / 32, DD / 32, 10), dim3(32, 8)>>>(qw, kvw);
    convert_split<<<(TOK * DD) / 4 / 256, 256>>>(x, 0);
    gemm3x_kernel<<<dim3(NQKV / 128, TOK / 128), 256, GSM_TOTAL>>>(nullptr, 0);

    rope_kernel<<<dim3(TOK, NHEAD + 1), 128>>>();

    // stage out_w transpose before flash (independent of flash output)
    transpose_outw<<<dim3(DD / 32, DD / 32), dim3(32, 8)>>>(ow);

    flash_kernel<<<dim3(TT / 64, NHEAD, BB), 256, FLASH_SMEM_BYTES>>>();

    // Out projection on HMMA
    convert_split<<<(TOK * DD) / 4 / 256, 256>>>(nullptr, 1);
    gemm3x_kernel<<<dim3(DD / 128, TOK / 128), 256, GSM_TOTAL>>>(out, 1);
}

// round 9
// speedup vs baseline: 4.6017x; 3.7482x over previous
#include <cuda_runtime.h>
#include <cuda_bf16.h>
#include <cuda_fp16.h>
#include <math.h>
#include <stdint.h>

// Problem constants
#define BB 2
#define TT 4096
#define DD 2048
#define NHEAD 8
#define HD 256
#define TOK (BB*TT)           // 8192
#define NQKV 2560             // 8*256 Q + 256 K + 256 V

// ---------------- scratch (device globals; no allocation allowed) ----------
__device__ float g_Q[(size_t)TOK * NHEAD * HD];   // 64 MiB
__device__ float g_K[(size_t)TOK * HD];           // 8 MiB
__device__ float g_V[(size_t)TOK * HD];           // 8 MiB
__device__ float g_enc[(size_t)TOK * NHEAD * HD]; // 64 MiB
// split-bf16 operands for HMMA GEMMs; g_Ahi/g_Alo reused as Qhi/Qlo for flash
__device__ __nv_bfloat16 g_Ahi[(size_t)TOK * DD];   // 32 MiB
__device__ __nv_bfloat16 g_Alo[(size_t)TOK * DD];   // 32 MiB
__device__ __nv_bfloat16 g_Bhi[(size_t)NQKV * DD];  // 10 MiB
__device__ __nv_bfloat16 g_Blo[(size_t)NQKV * DD];  // 10 MiB
// flash operands
__device__ __nv_bfloat16 g_Khi[(size_t)TOK * HD];   // 4 MiB
__device__ __nv_bfloat16 g_Klo[(size_t)TOK * HD];   // 4 MiB
__device__ __half        g_Vh [(size_t)TOK * HD];   // 4 MiB
__device__ float2        g_ropetab[(size_t)TT * 128]; // 4 MiB

// =================== ptx helpers ========================
__device__ __forceinline__ uint32_t s2u(const void* p) {
    uint32_t a;
    asm("{ .reg .u64 t; cvta.to.shared.u64 t, %1; cvt.u32.u64 %0, t; }"
        : "=r"(a) : "l"(p));
    return a;
}
__device__ __forceinline__ void cpa16(uint32_t s, const void* g) {
    asm volatile("cp.async.cg.shared.global [%0], [%1], 16;" :: "r"(s), "l"(g));
}
#define CP_COMMIT()  asm volatile("cp.async.commit_group;" ::: "memory")
#define CP_WAIT(N)   asm volatile("cp.async.wait_group %0;" :: "n"(N) : "memory")

#define LDSM4(r0, r1, r2, r3, addr) \
    asm volatile("ldmatrix.sync.aligned.m8n8.x4.shared.b16 {%0,%1,%2,%3}, [%4];" \
                 : "=r"(r0), "=r"(r1), "=r"(r2), "=r"(r3) : "r"(addr))

#define LDSM4T(r0, r1, r2, r3, addr) \
    asm volatile("ldmatrix.sync.aligned.m8n8.x4.trans.shared.b16 {%0,%1,%2,%3}, [%4];" \
                 : "=r"(r0), "=r"(r1), "=r"(r2), "=r"(r3) : "r"(addr))

#define MMA16816(d, a, b0, b1) \
    asm volatile("mma.sync.aligned.m16n8k16.row.col.f32.bf16.bf16.f32 " \
                 "{%0,%1,%2,%3}, {%4,%5,%6,%7}, {%8,%9}, {%0,%1,%2,%3};" \
                 : "+f"((d)[0]), "+f"((d)[1]), "+f"((d)[2]), "+f"((d)[3]) \
                 : "r"((a)[0]), "r"((a)[1]), "r"((a)[2]), "r"((a)[3]), \
                   "r"(b0), "r"(b1))

#define MMAF16(d, a, b0, b1) \
    asm volatile("mma.sync.aligned.m16n8k16.row.col.f32.f16.f16.f32 " \
                 "{%0,%1,%2,%3}, {%4,%5,%6,%7}, {%8,%9}, {%0,%1,%2,%3};" \
                 : "+f"((d)[0]), "+f"((d)[1]), "+f"((d)[2]), "+f"((d)[3]) \
                 : "r"((a)[0]), "r"((a)[1]), "r"((a)[2]), "r"((a)[3]), \
                   "r"(b0), "r"(b1))

// ===========================================================================
// Prep: transpose+split qkv weights into g_Bhi/g_Blo  ([N=2560][K=2048])
// ===========================================================================
__global__ void transpose_qkvw(const float* __restrict__ qw,
                               const float* __restrict__ kvw) {
    __shared__ float t[32][33];
    const int g = blockIdx.z;
    const float* slab = (g < 8) ? qw + (size_t)g * DD * HD
                                : kvw + (size_t)(g - 8) * DD * HD;
    const int h0 = blockIdx.x * 32, k0 = blockIdx.y * 32;
    const int c = threadIdx.x, r0 = threadIdx.y;   // (32,8)
#pragma unroll
    for (int i = 0; i < 32; i += 8)
        t[r0 + i][c] = slab[(size_t)(k0 + r0 + i) * HD + h0 + c];
    __syncthreads();
#pragma unroll
    for (int i = 0; i < 32; i += 8) {
        float v = t[c][r0 + i];
        size_t o = (size_t)(g * 256 + h0 + r0 + i) * DD + k0 + c;
        __nv_bfloat16 hi = __float2bfloat16(v);
        g_Bhi[o] = hi;
        g_Blo[o] = __float2bfloat16(v - __bfloat162float(hi));
    }
}

__global__ void transpose_outw(const float* __restrict__ ow) {
    __shared__ float t[32][33];
    const int j0 = blockIdx.x * 32, k0 = blockIdx.y * 32;
    const int c = threadIdx.x, r0 = threadIdx.y;
#pragma unroll
    for (int i = 0; i < 32; i += 8)
        t[r0 + i][c] = ow[(size_t)(k0 + r0 + i) * DD + j0 + c];
    __syncthreads();
#pragma unroll
    for (int i = 0; i < 32; i += 8) {
        float v = t[c][r0 + i];
        size_t o = (size_t)(j0 + r0 + i) * DD + k0 + c;
        __nv_bfloat16 hi = __float2bfloat16(v);
        g_Bhi[o] = hi;
        g_Blo[o] = __float2bfloat16(v - __bfloat162float(hi));
    }
}

// split activations (x or g_enc) into g_Ahi/g_Alo
__global__ void convert_split(const float* __restrict__ src, int use_enc) {
    const float* p = use_enc ? (const float*)g_enc : src;
    size_t i = (size_t)blockIdx.x * blockDim.x + threadIdx.x;   // float4 index
    float4 v = ((const float4*)p)[i];
    __nv_bfloat16 hx = __float2bfloat16(v.x), hy = __float2bfloat16(v.y);
    __nv_bfloat16 hz = __float2bfloat16(v.z), hw = __float2bfloat16(v.w);
    __nv_bfloat162* h2 = (__nv_bfloat162*)g_Ahi;
    __nv_bfloat162* l2 = (__nv_bfloat162*)g_Alo;
    h2[2 * i]     = __halves2bfloat162(hx, hy);
    h2[2 * i + 1] = __halves2bfloat162(hz, hw);
    l2[2 * i]     = __halves2bfloat162(
        __float2bfloat16(v.x - __bfloat162float(hx)),
        __float2bfloat16(v.y - __bfloat162float(hy)));
    l2[2 * i + 1] = __halves2bfloat162(
        __float2bfloat16(v.z - __bfloat162float(hz)),
        __float2bfloat16(v.w - __bfloat162float(hw)));
}

// ===========================================================================
// HMMA 3xBF16 GEMM (unchanged)
// ===========================================================================
#define KC 32
#define TROW 80
#define TILEB (128 * TROW)
#define STAGEB (4 * TILEB)
#define GSM_TOTAL (2 * STAGEB)

__device__ __forceinline__ void load_stage(uint32_t smb, int s, int k0, int tid,
                                           const __nv_bfloat16* const* base) {
    uint32_t sb = smb + s * STAGEB;
#pragma unroll
    for (int j = 0; j < 8; ++j) {
        int c = tid + j * 256;
        const int tile = j >> 1;
        int inner = c & 511;
        int row = inner >> 2, seg = inner & 3;
        const __nv_bfloat16* gp = base[tile] + (size_t)row * DD + k0 + seg * 8;
        cpa16(sb + tile * TILEB + row * TROW + seg * 16, gp);
    }
    CP_COMMIT();
}

__global__ __launch_bounds__(256, 1) void gemm3x_kernel(float* outp, int mode) {
    extern __shared__ __align__(128) char sm[];
    uint32_t smb = s2u(sm);
    const int tid = threadIdx.x;
    const int lane = tid & 31, wid = tid >> 5;
    const int wm = wid & 1, wn = wid >> 1;
    const int n0 = blockIdx.x * 128;
    const int m0 = blockIdx.y * 128;

    const __nv_bfloat16* base[4] = {
        g_Ahi + (size_t)m0 * DD, g_Alo + (size_t)m0 * DD,
        g_Bhi + (size_t)n0 * DD, g_Blo + (size_t)n0 * DD };

    float acc[4][4][4];
#pragma unroll
    for (int i = 0; i < 4; ++i)
#pragma unroll
        for (int j = 0; j < 4; ++j)
#pragma unroll
            for (int r = 0; r < 4; ++r) acc[i][j][r] = 0.f;

    const uint32_t a_off = (uint32_t)((wm * 64 + (lane & 15)) * TROW
                                      + (lane >> 4) * 16);
    const uint32_t b_off = (uint32_t)((wn * 32 + (lane >> 4) * 8 + (lane & 7)) * TROW
                                      + ((lane >> 3) & 1) * 16);

    load_stage(smb, 0, 0, tid, base);

    const int NIT = DD / KC;
    for (int it = 0; it < NIT; ++it) {
        const int s = it & 1;
        if (it + 1 < NIT) {
            load_stage(smb, s ^ 1, (it + 1) * KC, tid, base);
            CP_WAIT(1);
        } else {
            CP_WAIT(0);
        }
        __syncthreads();

        const uint32_t st = smb + s * STAGEB;
#pragma unroll
        for (int ks = 0; ks < 2; ++ks) {
            const uint32_t ko = ks * 32;
            uint32_t ahi[4][4], alo[4][4];
#pragma unroll
            for (int mf = 0; mf < 4; ++mf) {
                uint32_t aa = st + a_off + mf * (16 * TROW) + ko;
                LDSM4(ahi[mf][0], ahi[mf][1], ahi[mf][2], ahi[mf][3], aa);
                LDSM4(alo[mf][0], alo[mf][1], alo[mf][2], alo[mf][3], aa + TILEB);
            }
            uint32_t bhi[4][2], blo[4][2];
#pragma unroll
            for (int pr = 0; pr < 2; ++pr) {
                uint32_t ba = st + 2 * TILEB + b_off + pr * (16 * TROW) + ko;
                LDSM4(bhi[2 * pr][0], bhi[2 * pr][1],
                      bhi[2 * pr + 1][0], bhi[2 * pr + 1][1], ba);
                LDSM4(blo[2 * pr][0], blo[2 * pr][1],
                      blo[2 * pr + 1][0], blo[2 * pr + 1][1], ba + TILEB);
            }
#pragma unroll
            for (int mf = 0; mf < 4; ++mf)
#pragma unroll
                for (int nf = 0; nf < 4; ++nf) {
                    MMA16816(acc[mf][nf], ahi[mf], bhi[nf][0], bhi[nf][1]);
                    MMA16816(acc[mf][nf], ahi[mf], blo[nf][0], blo[nf][1]);
                    MMA16816(acc[mf][nf], alo[mf], bhi[nf][0], bhi[nf][1]);
                }
        }
        __syncthreads();
    }

    float* dst; int stride, colbase;
    if (mode == 0) {
        if (n0 < 2048)      { dst = g_Q; stride = NHEAD * HD; colbase = n0; }
        else if (n0 < 2304) { dst = g_K; stride = HD; colbase = n0 - 2048; }
        else                { dst = g_V; stride = HD; colbase = n0 - 2304; }
    } else { dst = outp; stride = DD; colbase = n0; }

    const int r0 = m0 + wm * 64 + (lane >> 2);
    const int c0 = colbase + wn * 32 + 2 * (lane & 3);
#pragma unroll
    for (int mf = 0; mf < 4; ++mf)
#pragma unroll
        for (int nf = 0; nf < 4; ++nf) {
            float* p0 = dst + (size_t)(r0 + mf * 16) * stride + c0 + nf * 8;
            *(float2*)p0 = make_float2(acc[mf][nf][0], acc[mf][nf][1]);
            float* p1 = p0 + 8 * stride;
            *(float2*)p1 = make_float2(acc[mf][nf][2], acc[mf][nf][3]);
        }
}

// ===========================================================================
// RoPE table (double precision, computed once per launch: 4096 x 128)
// ===========================================================================
__global__ void rope_table() {
    int t = blockIdx.x, i = threadIdx.x;
    double inv = pow(10000.0, -(double)i / 128.0);
    double ang = (double)t * inv;
    g_ropetab[t * 128 + i] = make_float2((float)sin(ang), (float)cos(ang));
}

// rope + 1/16 scale + bf16 split: g_Q -> g_Ahi/g_Alo (layout [tok][n*256+h])
__global__ void qropesplit() {
    const int tok = blockIdx.x, n = blockIdx.y, i = threadIdx.x;
    const int t = tok & (TT - 1);
    float2 sc = g_ropetab[t * 128 + i];
    size_t o = (size_t)tok * 2048 + n * 256;
    float a = g_Q[o + i], b = g_Q[o + i + 128];
    float r1 = (a * sc.y - b * sc.x) * 0.0625f;
    float r2 = (b * sc.y + a * sc.x) * 0.0625f;
    __nv_bfloat16 h1 = __float2bfloat16(r1);
    g_Ahi[o + i] = h1;
    g_Alo[o + i] = __float2bfloat16(r1 - __bfloat162float(h1));
    __nv_bfloat16 h2 = __float2bfloat16(r2);
    g_Ahi[o + i + 128] = h2;
    g_Alo[o + i + 128] = __float2bfloat16(r2 - __bfloat162float(h2));
}

// rope + bf16 split: g_K -> g_Khi/g_Klo
__global__ void kropesplit() {
    const int tok = blockIdx.x, i = threadIdx.x;
    const int t = tok & (TT - 1);
    float2 sc = g_ropetab[t * 128 + i];
    size_t o = (size_t)tok * 256;
    float a = g_K[o + i], b = g_K[o + i + 128];
    float r1 = a * sc.y - b * sc.x;
    float r2 = b * sc.y + a * sc.x;
    __nv_bfloat16 h1 = __float2bfloat16(r1);
    g_Khi[o + i] = h1;
    g_Klo[o + i] = __float2bfloat16(r1 - __bfloat162float(h1));
    __nv_bfloat16 h2 = __float2bfloat16(r2);
    g_Khi[o + i + 128] = h2;
    g_Klo[o + i + 128] = __float2bfloat16(r2 - __bfloat162float(h2));
}

// V -> fp16
__global__ void vconv() {
    size_t i = (size_t)blockIdx.x * blockDim.x + threadIdx.x;   // float4 idx
    float4 v = ((const float4*)g_V)[i];
    __half2* d = (__half2*)g_Vh;
    d[2 * i]     = __floats2half2_rn(v.x, v.y);
    d[2 * i + 1] = __floats2half2_rn(v.z, v.w);
}

// ===========================================================================
// HMMA causal flash attention.
// CTA: 64 q-rows x 1 head. 256 threads = 8 warps: wm=wid>>1 (16-row group),
// wn=wid&1.  QK^T: 3xbf16 split, warp tile m16 x n16 of 32-key tile.
// PV: fp16 P (hi+lo) x fp16 V (ldmatrix.trans), warp tile m16 x n128.
// K/V double-buffered cp.async; O register-resident (64 f32/thread).
// K/V smem rows 528B pitch, P rows 80B pitch (both 16B-multiples: ldmatrix
// requires 16B-aligned row addresses — 72B pitch was the R7 fault).
// ===========================================================================
#define BN 32
#define KST 528
#define PST 80
#define ST_KHI(s) ((s)*50688)
#define ST_KLO(s) (ST_KHI(s)+16896)
#define ST_VH(s)  (ST_KHI(s)+33792)
#define SQLO   101376
#define SPHI   135168
#define SPLO   (SPHI + 64*PST)      // 140288
#define SRED   (SPLO + 64*PST)      // 145408
#define FLASH_SMEM (SRED + 1024)    // 146432

__device__ __forceinline__ void flash_load(uint32_t smb, int s, int s0, int tid,
                                           const __nv_bfloat16* kh,
                                           const __nv_bfloat16* kl,
                                           const __half* vh) {
#pragma unroll
    for (int i2 = 0; i2 < 4; ++i2) {
        int c = tid + i2 * 256;
        int row = c >> 5, seg = c & 31;
        size_t go = (size_t)(s0 + row) * 512 + seg * 16;   // bytes
        uint32_t so = row * KST + seg * 16;
        cpa16(smb + ST_KHI(s) + so, (const char*)kh + go);
        cpa16(smb + ST_KLO(s) + so, (const char*)kl + go);
        cpa16(smb + ST_VH(s)  + so, (const char*)vh + go);
    }
}

__global__ __launch_bounds__(256) void flash_hmma() {
    extern __shared__ __align__(128) char sm[];
    uint32_t smb = s2u(sm);
    const int tid = threadIdx.x, lane = tid & 31, wid = tid >> 5;
    const int wm = wid >> 1, wn = wid & 1;
    const int bx = gridDim.x - 1 - blockIdx.x;    // heavy tiles first
    const int n = blockIdx.y, b = blockIdx.z;
    const int q0 = bx * 64;
    const size_t tb = (size_t)b * TT;

    const char* qh_g = (const char*)(g_Ahi + (size_t)(tb + q0) * 2048 + n * 256);
    const char* ql_g = (const char*)(g_Alo + (size_t)(tb + q0) * 2048 + n * 256);
    const __nv_bfloat16* kh_g = g_Khi + tb * 256;
    const __nv_bfloat16* kl_g = g_Klo + tb * 256;
    const __half* vh_g = g_Vh + tb * 256;

    // ---- stage Q: hi -> stage1 K area (transient), lo -> persistent SQLO
#pragma unroll
    for (int i2 = 0; i2 < 8; ++i2) {
        int c = tid + i2 * 256;
        int row = c >> 5, seg = c & 31;
        cpa16(smb + ST_KHI(1) + row * KST + seg * 16, qh_g + (size_t)row * 4096 + seg * 16);
        cpa16(smb + SQLO + row * KST + seg * 16,      ql_g + (size_t)row * 4096 + seg * 16);
    }
    CP_COMMIT();
    CP_WAIT(0);
    __syncthreads();

    const uint32_t a_base = (uint32_t)((wm * 16 + (lane & 15)) * KST + (lane >> 4) * 16);
    uint32_t qh[16][4];
#pragma unroll
    for (int ks = 0; ks < 16; ++ks)
        LDSM4(qh[ks][0], qh[ks][1], qh[ks][2], qh[ks][3],
              smb + ST_KHI(1) + a_base + ks * 32);
    __syncthreads();   // Qhi consumed; stage1 free for K/V

    flash_load(smb, 0, 0, tid, kh_g, kl_g, vh_g);
    CP_COMMIT();

    float o[16][4];
#pragma unroll
    for (int nf = 0; nf < 16; ++nf)
#pragma unroll
        for (int r = 0; r < 4; ++r) o[nf][r] = 0.f;
    float m1 = -1e30f, m2 = -1e30f, l1 = 0.f, l2 = 0.f;

    const int grow1 = wm * 16 + (lane >> 2);
    const int grow2 = grow1 + 8;
    const int ccol = 2 * (lane & 3);
    float* rmaxs = (float*)(sm + SRED);
    float* rsums = (float*)(sm + SRED + 512);
    const uint32_t b_base = (uint32_t)((wn * 16 + ((lane >> 4) << 3) + (lane & 7)) * KST
                                       + ((lane >> 3) & 1) * 16);
    const uint32_t p_base = (uint32_t)((wm * 16 + (lane & 15)) * PST + (lane >> 4) * 16);
    const uint32_t v_base = (uint32_t)((lane & 15) * KST + wn * 256 + (lane >> 4) * 16);

    const int ntiles = 2 * bx + 2;
    for (int kt = 0; kt < ntiles; ++kt) {
        const int s = kt & 1;
        CP_WAIT(0);
        __syncthreads();   // K/V stage s ready; prev PV & smem reuse safe
        if (kt + 1 < ntiles) {
            flash_load(smb, s ^ 1, (kt + 1) * BN, tid, kh_g, kl_g, vh_g);
            CP_COMMIT();
        }

        // ---- S = Q K^T (3x split)
        float sa[2][4];
#pragma unroll
        for (int nf = 0; nf < 2; ++nf)
#pragma unroll
            for (int r = 0; r < 4; ++r) sa[nf][r] = 0.f;
#pragma unroll
        for (int ks = 0; ks < 16; ++ks) {
            uint32_t ql[4];
            LDSM4(ql[0], ql[1], ql[2], ql[3], smb + SQLO + a_base + ks * 32);
            uint32_t bh0, bh1, bh2, bh3, bl0, bl1, bl2, bl3;
            LDSM4(bh0, bh1, bh2, bh3, smb + ST_KHI(s) + b_base + ks * 32);
            LDSM4(bl0, bl1, bl2, bl3, smb + ST_KLO(s) + b_base + ks * 32);
            MMA16816(sa[0], qh[ks], bh0, bh1);
            MMA16816(sa[1], qh[ks], bh2, bh3);
            MMA16816(sa[0], qh[ks], bl0, bl1);
            MMA16816(sa[1], qh[ks], bl2, bl3);
            MMA16816(sa[0], ql, bh0, bh1);
            MMA16816(sa[1], ql, bh2, bh3);
        }

        // ---- causal mask (only possible on last two tiles)
        const int s0 = kt * BN;
        if (kt >= 2 * bx) {
            const int qr1 = q0 + grow1, qr2 = q0 + grow2;
#pragma unroll
            for (int nf = 0; nf < 2; ++nf) {
                int c0 = s0 + wn * 16 + nf * 8 + ccol;
                if (c0     > qr1) sa[nf][0] = -1e30f;
                if (c0 + 1 > qr1) sa[nf][1] = -1e30f;
                if (c0     > qr2) sa[nf][2] = -1e30f;
                if (c0 + 1 > qr2) sa[nf][3] = -1e30f;
            }
        }

        // ---- online softmax
        float pm1 = fmaxf(fmaxf(sa[0][0], sa[0][1]), fmaxf(sa[1][0], sa[1][1]));
        float pm2 = fmaxf(fmaxf(sa[0][2], sa[0][3]), fmaxf(sa[1][2], sa[1][3]));
        pm1 = fmaxf(pm1, __shfl_xor_sync(0xffffffffu, pm1, 1));
        pm1 = fmaxf(pm1, __shfl_xor_sync(0xffffffffu, pm1, 2));
        pm2 = fmaxf(pm2, __shfl_xor_sync(0xffffffffu, pm2, 1));
        pm2 = fmaxf(pm2, __shfl_xor_sync(0xffffffffu, pm2, 2));
        if ((lane & 3) == 0) {
            rmaxs[wn * 64 + grow1] = pm1;
            rmaxs[wn * 64 + grow2] = pm2;
        }
        __syncthreads();
        float mn1 = fmaxf(m1, fmaxf(rmaxs[grow1], rmaxs[64 + grow1]));
        float mn2 = fmaxf(m2, fmaxf(rmaxs[grow2], rmaxs[64 + grow2]));
        float al1 = __expf(m1 - mn1), al2 = __expf(m2 - mn2);
        m1 = mn1; m2 = mn2;

        float ps1 = 0.f, ps2 = 0.f;
#pragma unroll
        for (int nf = 0; nf < 2; ++nf) {
            float e0 = __expf(sa[nf][0] - mn1), e1 = __expf(sa[nf][1] - mn1);
            float e2 = __expf(sa[nf][2] - mn2), e3 = __expf(sa[nf][3] - mn2);
            ps1 += e0 + e1; ps2 += e2 + e3;
            __half h0 = __float2half_rn(e0), h1 = __float2half_rn(e1);
            __half h2 = __float2half_rn(e2), h3 = __float2half_rn(e3);
            int colB = (wn * 16 + nf * 8 + ccol) * 2;
            *(__half2*)(sm + SPHI + grow1 * PST + colB) = __halves2half2(h0, h1);
            *(__half2*)(sm + SPHI + grow2 * PST + colB) = __halves2half2(h2, h3);
            __half g0 = __float2half_rn(e0 - __half2float(h0));
            __half g1 = __float2half_rn(e1 - __half2float(h1));
            __half g2 = __float2half_rn(e2 - __half2float(h2));
            __half g3 = __float2half_rn(e3 - __half2float(h3));
            *(__half2*)(sm + SPLO + grow1 * PST + colB) = __halves2half2(g0, g1);
            *(__half2*)(sm + SPLO + grow2 * PST + colB) = __halves2half2(g2, g3);
        }
        ps1 += __shfl_xor_sync(0xffffffffu, ps1, 1);
        ps1 += __shfl_xor_sync(0xffffffffu, ps1, 2);
        ps2 += __shfl_xor_sync(0xffffffffu, ps2, 1);
        ps2 += __shfl_xor_sync(0xffffffffu, ps2, 2);
        if ((lane & 3) == 0) {
            rsums[wn * 64 + grow1] = ps1;
            rsums[wn * 64 + grow2] = ps2;
        }
        // rescale O
#pragma unroll
        for (int nf = 0; nf < 16; ++nf) {
            o[nf][0] *= al1; o[nf][1] *= al1;
            o[nf][2] *= al2; o[nf][3] *= al2;
        }
        __syncthreads();
        l1 = l1 * al1 + rsums[grow1] + rsums[64 + grow1];
        l2 = l2 * al2 + rsums[grow2] + rsums[64 + grow2];

        // ---- O += P V  (fp16, P split hi+lo)
#pragma unroll
        for (int ks = 0; ks < 2; ++ks) {
            uint32_t ph[4], pl[4];
            LDSM4(ph[0], ph[1], ph[2], ph[3], smb + SPHI + p_base + ks * 32);
            LDSM4(pl[0], pl[1], pl[2], pl[3], smb + SPLO + p_base + ks * 32);
#pragma unroll
            for (int nb = 0; nb < 8; ++nb) {
                uint32_t v0, v1, v2, v3;
                LDSM4T(v0, v1, v2, v3,
                       smb + ST_VH(s) + v_base + ks * (16 * KST) + nb * 32);
                MMAF16(o[2 * nb],     ph, v0, v1);
                MMAF16(o[2 * nb + 1], ph, v2, v3);
                MMAF16(o[2 * nb],     pl, v0, v1);
                MMAF16(o[2 * nb + 1], pl, v2, v3);
            }
        }
    }

    // ---- epilogue: normalize, write g_enc fp32
    float i1 = 1.f / l1, i2 = 1.f / l2;
#pragma unroll
    for (int nf = 0; nf < 16; ++nf) {
        int col = wn * 128 + nf * 8 + ccol;
        float* p1 = &g_enc[((tb + q0 + grow1) * NHEAD + n) * HD + col];
        *(float2*)p1 = make_float2(o[nf][0] * i1, o[nf][1] * i1);
        float* p2 = &g_enc[((tb + q0 + grow2) * NHEAD + n) * HD + col];
        *(float2*)p2 = make_float2(o[nf][2] * i2, o[nf][3] * i2);
    }
}

// ===========================================================================
// launch — inputs: 0=x, 1=segment_pos, 2=attn_mask, 3=q_w, 4=kv_w, 5=out_w
// ===========================================================================
extern "C" void kernel_launch(void* const* d_in, const int* in_sizes, int n_in,
                              void* d_out, int out_size) {
    (void)in_sizes; (void)n_in; (void)out_size;
    const float* x   = (const float*)d_in[0];
    const float* qw  = (const float*)d_in[3];
    const float* kvw = (const float*)d_in[4];
    const float* ow  = (const float*)d_in[5];
    float* out = (float*)d_out;

    cudaFuncSetAttribute(gemm3x_kernel,
                         cudaFuncAttributeMaxDynamicSharedMemorySize, GSM_TOTAL);
    cudaFuncSetAttribute(flash_hmma,
                         cudaFuncAttributeMaxDynamicSharedMemorySize, FLASH_SMEM);

    // QKV projection (HMMA 3xBF16)
    transpose_qkvw<<<dim3(HD / 32, DD / 32, 10), dim3(32, 8)>>>(qw, kvw);
    convert_split<<<(TOK * DD) / 4 / 256, 256>>>(x, 0);
    gemm3x_kernel<<<dim3(NQKV / 128, TOK / 128), 256, GSM_TOTAL>>>(nullptr, 0);

    // RoPE table + fused rope/scale/split converts
    rope_table<<<TT, 128>>>();
    qropesplit<<<dim3(TOK, NHEAD), 128>>>();
    kropesplit<<<TOK, 128>>>();
    vconv<<<(TOK * HD) / 4 / 256, 256>>>();

    transpose_outw<<<dim3(DD / 32, DD / 32), dim3(32, 8)>>>(ow);

    // HMMA flash attention
    flash_hmma<<<dim3(TT / 64, NHEAD, BB), 256, FLASH_SMEM>>>();

    // Out projection (HMMA 3xBF16)
    convert_split<<<(TOK * DD) / 4 / 256, 256>>>(nullptr, 1);
    gemm3x_kernel<<<dim3(DD / 128, TOK / 128), 256, GSM_TOTAL>>>(out, 1);
}

// round 10
// speedup vs baseline: 5.0788x; 1.1037x over previous
#include <cuda_runtime.h>
#include <cuda_bf16.h>
#include <cuda_fp16.h>
#include <math.h>
#include <stdint.h>

// Problem constants
#define BB 2
#define TT 4096
#define DD 2048
#define NHEAD 8
#define HD 256
#define TOK (BB*TT)           // 8192
#define NQKV 2560             // 8*256 Q + 256 K + 256 V

// ---------------- scratch (device globals; no allocation allowed) ----------
// Q (rope'd, scaled, bf16 split, head-interleaved cols): hi then lo halves
__device__ __nv_bfloat16 g_Qsp[(size_t)2 * TOK * DD];   // 64 MiB
// A operands for GEMMs: x-split, later overwritten by enc-split (flash output)
__device__ __nv_bfloat16 g_Ahi[(size_t)TOK * DD];       // 32 MiB
__device__ __nv_bfloat16 g_Alo[(size_t)TOK * DD];       // 32 MiB
// B operands (weights, K-major)
__device__ __nv_bfloat16 g_Bhi[(size_t)NQKV * DD];      // 10 MiB
__device__ __nv_bfloat16 g_Blo[(size_t)NQKV * DD];      // 10 MiB
// flash K/V operands (K head-interleaved like Q; V natural)
__device__ __nv_bfloat16 g_Khi[(size_t)TOK * HD];       // 4 MiB
__device__ __nv_bfloat16 g_Klo[(size_t)TOK * HD];       // 4 MiB
__device__ __half        g_Vh [(size_t)TOK * HD];       // 4 MiB
__device__ float2        g_ropetab[(size_t)TT * 128];   // 4 MiB

// =================== ptx helpers ========================
__device__ __forceinline__ uint32_t s2u(const void* p) {
    uint32_t a;
    asm("{ .reg .u64 t; cvta.to.shared.u64 t, %1; cvt.u32.u64 %0, t; }"
        : "=r"(a) : "l"(p));
    return a;
}
__device__ __forceinline__ void cpa16(uint32_t s, const void* g) {
    asm volatile("cp.async.cg.shared.global [%0], [%1], 16;" :: "r"(s), "l"(g));
}
#define CP_COMMIT()  asm volatile("cp.async.commit_group;" ::: "memory")
#define CP_WAIT(N)   asm volatile("cp.async.wait_group %0;" :: "n"(N) : "memory")

#define LDSM4(r0, r1, r2, r3, addr) \
    asm volatile("ldmatrix.sync.aligned.m8n8.x4.shared.b16 {%0,%1,%2,%3}, [%4];" \
                 : "=r"(r0), "=r"(r1), "=r"(r2), "=r"(r3) : "r"(addr))

#define LDSM4T(r0, r1, r2, r3, addr) \
    asm volatile("ldmatrix.sync.aligned.m8n8.x4.trans.shared.b16 {%0,%1,%2,%3}, [%4];" \
                 : "=r"(r0), "=r"(r1), "=r"(r2), "=r"(r3) : "r"(addr))

#define MMA16816(d, a, b0, b1) \
    asm volatile("mma.sync.aligned.m16n8k16.row.col.f32.bf16.bf16.f32 " \
                 "{%0,%1,%2,%3}, {%4,%5,%6,%7}, {%8,%9}, {%0,%1,%2,%3};" \
                 : "+f"((d)[0]), "+f"((d)[1]), "+f"((d)[2]), "+f"((d)[3]) \
                 : "r"((a)[0]), "r"((a)[1]), "r"((a)[2]), "r"((a)[3]), \
                   "r"(b0), "r"(b1))

#define MMAF16(d, a, b0, b1) \
    asm volatile("mma.sync.aligned.m16n8k16.row.col.f32.f16.f16.f32 " \
                 "{%0,%1,%2,%3}, {%4,%5,%6,%7}, {%8,%9}, {%0,%1,%2,%3};" \
                 : "+f"((d)[0]), "+f"((d)[1]), "+f"((d)[2]), "+f"((d)[3]) \
                 : "r"((a)[0]), "r"((a)[1]), "r"((a)[2]), "r"((a)[3]), \
                   "r"(b0), "r"(b1))

// ===========================================================================
// RoPE table: angle = t * 10000^{-i/128}.  Exact range reduction in double
// (one DP pow per block, one DP mul+frac per element), fp32 sincospi.
// ===========================================================================
__global__ void rope_table() {
    __shared__ double u1s;
    const int i = blockIdx.x;
    if (threadIdx.x == 0)
        u1s = pow(10000.0, -(double)i / 128.0) * 0.15915494309189533576;  // inv/(2*pi)
    __syncthreads();
    const double u1 = u1s;
    for (int t = threadIdx.x; t < TT; t += blockDim.x) {
        double u = (double)t * u1;
        float x2 = (float)(2.0 * (u - trunc(u)));   // [0,2): angle/pi mod 2
        float s, c;
        sincospif(x2, &s, &c);
        g_ropetab[t * 128 + i] = make_float2(s, c);
    }
}

// ===========================================================================
// Prep: transpose+split qkv weights into g_Bhi/g_Blo  ([N=2560][K=2048]).
// Q/K heads column-INTERLEAVED: h -> (h<128 ? 2h : 2(h-128)+1), so rope
// pairs (h, h+128) land on adjacent output cols (same MMA c-fragment).
// ===========================================================================
__global__ void transpose_qkvw(const float* __restrict__ qw,
                               const float* __restrict__ kvw) {
    __shared__ float t[32][33];
    const int g = blockIdx.z;
    const float* slab = (g < 8) ? qw + (size_t)g * DD * HD
                                : kvw + (size_t)(g - 8) * DD * HD;
    const int h0 = blockIdx.x * 32, k0 = blockIdx.y * 32;
    const int c = threadIdx.x, r0 = threadIdx.y;   // (32,8)
#pragma unroll
    for (int i = 0; i < 32; i += 8)
        t[r0 + i][c] = slab[(size_t)(k0 + r0 + i) * HD + h0 + c];
    __syncthreads();
#pragma unroll
    for (int i = 0; i < 32; i += 8) {
        float v = t[c][r0 + i];
        int h = h0 + r0 + i;
        int hp = (g == 9) ? h : ((h < 128) ? 2 * h : 2 * (h - 128) + 1);
        size_t o = (size_t)(g * 256 + hp) * DD + k0 + c;
        __nv_bfloat16 hi = __float2bfloat16(v);
        g_Bhi[o] = hi;
        g_Blo[o] = __float2bfloat16(v - __bfloat162float(hi));
    }
}

// transpose+split out_w ([k=nh 2048][d 2048]) -> g_Bhi/lo [d][nh] (natural)
__global__ void transpose_outw(const float* __restrict__ ow) {
    __shared__ float t[32][33];
    const int j0 = blockIdx.x * 32, k0 = blockIdx.y * 32;
    const int c = threadIdx.x, r0 = threadIdx.y;
#pragma unroll
    for (int i = 0; i < 32; i += 8)
        t[r0 + i][c] = ow[(size_t)(k0 + r0 + i) * DD + j0 + c];
    __syncthreads();
#pragma unroll
    for (int i = 0; i < 32; i += 8) {
        float v = t[c][r0 + i];
        size_t o = (size_t)(j0 + r0 + i) * DD + k0 + c;
        __nv_bfloat16 hi = __float2bfloat16(v);
        g_Bhi[o] = hi;
        g_Blo[o] = __float2bfloat16(v - __bfloat162float(hi));
    }
}

// split x into g_Ahi/g_Alo
__global__ void convert_split(const float* __restrict__ src) {
    size_t i = (size_t)blockIdx.x * blockDim.x + threadIdx.x;   // float4 index
    float4 v = ((const float4*)src)[i];
    __nv_bfloat16 hx = __float2bfloat16(v.x), hy = __float2bfloat16(v.y);
    __nv_bfloat16 hz = __float2bfloat16(v.z), hw = __float2bfloat16(v.w);
    __nv_bfloat162* h2 = (__nv_bfloat162*)g_Ahi;
    __nv_bfloat162* l2 = (__nv_bfloat162*)g_Alo;
    h2[2 * i]     = __halves2bfloat162(hx, hy);
    h2[2 * i + 1] = __halves2bfloat162(hz, hw);
    l2[2 * i]     = __halves2bfloat162(
        __float2bfloat16(v.x - __bfloat162float(hx)),
        __float2bfloat16(v.y - __bfloat162float(hy)));
    l2[2 * i + 1] = __halves2bfloat162(
        __float2bfloat16(v.z - __bfloat162float(hz)),
        __float2bfloat16(v.w - __bfloat162float(hw)));
}

// ===========================================================================
// HMMA 3xBF16 GEMM.  mode 0 (qkv): fused epilogue — rope+scale+split Q ->
// g_Qsp, rope+split K -> g_Khi/lo, fp16 V -> g_Vh.   mode 1: fp32 -> outp.
// ===========================================================================
#define KC 32
#define TROW 80
#define TILEB (128 * TROW)
#define STAGEB (4 * TILEB)
#define GSM_TOTAL (2 * STAGEB)

__device__ __forceinline__ void load_stage(uint32_t smb, int s, int k0, int tid,
                                           const __nv_bfloat16* const* base) {
    uint32_t sb = smb + s * STAGEB;
#pragma unroll
    for (int j = 0; j < 8; ++j) {
        int c = tid + j * 256;
        const int tile = j >> 1;
        int inner = c & 511;
        int row = inner >> 2, seg = inner & 3;
        const __nv_bfloat16* gp = base[tile] + (size_t)row * DD + k0 + seg * 8;
        cpa16(sb + tile * TILEB + row * TROW + seg * 16, gp);
    }
    CP_COMMIT();
}

__global__ __launch_bounds__(256, 1) void gemm3x_kernel(float* outp, int mode) {
    extern __shared__ __align__(128) char sm[];
    uint32_t smb = s2u(sm);
    const int tid = threadIdx.x;
    const int lane = tid & 31, wid = tid >> 5;
    const int wm = wid & 1, wn = wid >> 1;
    const int n0 = blockIdx.x * 128;
    const int m0 = blockIdx.y * 128;

    const __nv_bfloat16* base[4] = {
        g_Ahi + (size_t)m0 * DD, g_Alo + (size_t)m0 * DD,
        g_Bhi + (size_t)n0 * DD, g_Blo + (size_t)n0 * DD };

    float acc[4][4][4];
#pragma unroll
    for (int i = 0; i < 4; ++i)
#pragma unroll
        for (int j = 0; j < 4; ++j)
#pragma unroll
            for (int r = 0; r < 4; ++r) acc[i][j][r] = 0.f;

    const uint32_t a_off = (uint32_t)((wm * 64 + (lane & 15)) * TROW
                                      + (lane >> 4) * 16);
    const uint32_t b_off = (uint32_t)((wn * 32 + (lane >> 4) * 8 + (lane & 7)) * TROW
                                      + ((lane >> 3) & 1) * 16);

    load_stage(smb, 0, 0, tid, base);

    const int NIT = DD / KC;
    for (int it = 0; it < NIT; ++it) {
        const int s = it & 1;
        if (it + 1 < NIT) {
            load_stage(smb, s ^ 1, (it + 1) * KC, tid, base);
            CP_WAIT(1);
        } else {
            CP_WAIT(0);
        }
        __syncthreads();

        const uint32_t st = smb + s * STAGEB;
#pragma unroll
        for (int ks = 0; ks < 2; ++ks) {
            const uint32_t ko = ks * 32;
            uint32_t ahi[4][4], alo[4][4];
#pragma unroll
            for (int mf = 0; mf < 4; ++mf) {
                uint32_t aa = st + a_off + mf * (16 * TROW) + ko;
                LDSM4(ahi[mf][0], ahi[mf][1], ahi[mf][2], ahi[mf][3], aa);
                LDSM4(alo[mf][0], alo[mf][1], alo[mf][2], alo[mf][3], aa + TILEB);
            }
            uint32_t bhi[4][2], blo[4][2];
#pragma unroll
            for (int pr = 0; pr < 2; ++pr) {
                uint32_t ba = st + 2 * TILEB + b_off + pr * (16 * TROW) + ko;
                LDSM4(bhi[2 * pr][0], bhi[2 * pr][1],
                      bhi[2 * pr + 1][0], bhi[2 * pr + 1][1], ba);
                LDSM4(blo[2 * pr][0], blo[2 * pr][1],
                      blo[2 * pr + 1][0], blo[2 * pr + 1][1], ba + TILEB);
            }
#pragma unroll
            for (int mf = 0; mf < 4; ++mf)
#pragma unroll
                for (int nf = 0; nf < 4; ++nf) {
                    MMA16816(acc[mf][nf], ahi[mf], bhi[nf][0], bhi[nf][1]);
                    MMA16816(acc[mf][nf], ahi[mf], blo[nf][0], blo[nf][1]);
                    MMA16816(acc[mf][nf], alo[mf], bhi[nf][0], bhi[nf][1]);
                }
        }
        __syncthreads();
    }

    const int r0 = m0 + wm * 64 + (lane >> 2);
    const int lc0 = wn * 32 + 2 * (lane & 3);

    if (mode == 1) {
        const int c0 = n0 + lc0;
#pragma unroll
        for (int mf = 0; mf < 4; ++mf)
#pragma unroll
            for (int nf = 0; nf < 4; ++nf) {
                float* p0 = outp + (size_t)(r0 + mf * 16) * DD + c0 + nf * 8;
                *(float2*)p0 = make_float2(acc[mf][nf][0], acc[mf][nf][1]);
                float* p1 = p0 + 8 * DD;
                *(float2*)p1 = make_float2(acc[mf][nf][2], acc[mf][nf][3]);
            }
    } else if (n0 < 2048) {
        // Q: rope + 1/16 scale + bf16 split (cols interleaved: pair = (h, h+128))
        __nv_bfloat16* Qhi = g_Qsp;
        __nv_bfloat16* Qlo = g_Qsp + (size_t)TOK * DD;
#pragma unroll
        for (int mf = 0; mf < 4; ++mf)
#pragma unroll
            for (int nf = 0; nf < 4; ++nf) {
                int row1 = r0 + mf * 16, row2 = row1 + 8;
                int col = n0 + lc0 + nf * 8;
                int ri = (col & 255) >> 1;
                float2 sc1 = g_ropetab[(row1 & (TT - 1)) * 128 + ri];
                float2 sc2 = g_ropetab[(row2 & (TT - 1)) * 128 + ri];
                float a1 = acc[mf][nf][0], b1 = acc[mf][nf][1];
                float a2 = acc[mf][nf][2], b2 = acc[mf][nf][3];
                float x1 = (a1 * sc1.y - b1 * sc1.x) * 0.0625f;
                float y1 = (b1 * sc1.y + a1 * sc1.x) * 0.0625f;
                float x2 = (a2 * sc2.y - b2 * sc2.x) * 0.0625f;
                float y2 = (b2 * sc2.y + a2 * sc2.x) * 0.0625f;
                __nv_bfloat16 hx1 = __float2bfloat16(x1), hy1 = __float2bfloat16(y1);
                __nv_bfloat16 hx2 = __float2bfloat16(x2), hy2 = __float2bfloat16(y2);
                *(__nv_bfloat162*)&Qhi[(size_t)row1 * DD + col] = __halves2bfloat162(hx1, hy1);
                *(__nv_bfloat162*)&Qhi[(size_t)row2 * DD + col] = __halves2bfloat162(hx2, hy2);
                *(__nv_bfloat162*)&Qlo[(size_t)row1 * DD + col] = __halves2bfloat162(
                    __float2bfloat16(x1 - __bfloat162float(hx1)),
                    __float2bfloat16(y1 - __bfloat162float(hy1)));
                *(__nv_bfloat162*)&Qlo[(size_t)row2 * DD + col] = __halves2bfloat162(
                    __float2bfloat16(x2 - __bfloat162float(hx2)),
                    __float2bfloat16(y2 - __bfloat162float(hy2)));
            }
    } else if (n0 < 2304) {
        // K: rope + bf16 split (interleaved cols)
#pragma unroll
        for (int mf = 0; mf < 4; ++mf)
#pragma unroll
            for (int nf = 0; nf < 4; ++nf) {
                int row1 = r0 + mf * 16, row2 = row1 + 8;
                int col = (n0 - 2048) + lc0 + nf * 8;    // [0,256)
                int ri = col >> 1;
                float2 sc1 = g_ropetab[(row1 & (TT - 1)) * 128 + ri];
                float2 sc2 = g_ropetab[(row2 & (TT - 1)) * 128 + ri];
                float a1 = acc[mf][nf][0], b1 = acc[mf][nf][1];
                float a2 = acc[mf][nf][2], b2 = acc[mf][nf][3];
                float x1 = a1 * sc1.y - b1 * sc1.x;
                float y1 = b1 * sc1.y + a1 * sc1.x;
                float x2 = a2 * sc2.y - b2 * sc2.x;
                float y2 = b2 * sc2.y + a2 * sc2.x;
                __nv_bfloat16 hx1 = __float2bfloat16(x1), hy1 = __float2bfloat16(y1);
                __nv_bfloat16 hx2 = __float2bfloat16(x2), hy2 = __float2bfloat16(y2);
                *(__nv_bfloat162*)&g_Khi[(size_t)row1 * HD + col] = __halves2bfloat162(hx1, hy1);
                *(__nv_bfloat162*)&g_Khi[(size_t)row2 * HD + col] = __halves2bfloat162(hx2, hy2);
                *(__nv_bfloat162*)&g_Klo[(size_t)row1 * HD + col] = __halves2bfloat162(
                    __float2bfloat16(x1 - __bfloat162float(hx1)),
                    __float2bfloat16(y1 - __bfloat162float(hy1)));
                *(__nv_bfloat162*)&g_Klo[(size_t)row2 * HD + col] = __halves2bfloat162(
                    __float2bfloat16(x2 - __bfloat162float(hx2)),
                    __float2bfloat16(y2 - __bfloat162float(hy2)));
            }
    } else {
        // V: fp16, natural cols
#pragma unroll
        for (int mf = 0; mf < 4; ++mf)
#pragma unroll
            for (int nf = 0; nf < 4; ++nf) {
                int row1 = r0 + mf * 16, row2 = row1 + 8;
                int col = (n0 - 2304) + lc0 + nf * 8;
                *(__half2*)&g_Vh[(size_t)row1 * HD + col] =
                    __floats2half2_rn(acc[mf][nf][0], acc[mf][nf][1]);
                *(__half2*)&g_Vh[(size_t)row2 * HD + col] =
                    __floats2half2_rn(acc[mf][nf][2], acc[mf][nf][3]);
            }
    }
}

// ===========================================================================
// HMMA causal flash attention (as R9, minus Plo; epilogue writes enc bf16
// split straight into g_Ahi/g_Alo for the out-projection).
// ===========================================================================
#define BN 32
#define KST 528
#define PST 80
#define ST_KHI(s) ((s)*50688)
#define ST_KLO(s) (ST_KHI(s)+16896)
#define ST_VH(s)  (ST_KHI(s)+33792)
#define SQLO   101376
#define SPHI   135168
#define SRED   (SPHI + 64*PST)      // 140288
#define FLASH_SMEM (SRED + 1024)    // 141312

__device__ __forceinline__ void flash_load(uint32_t smb, int s, int s0, int tid,
                                           const __nv_bfloat16* kh,
                                           const __nv_bfloat16* kl,
                                           const __half* vh) {
#pragma unroll
    for (int i2 = 0; i2 < 4; ++i2) {
        int c = tid + i2 * 256;
        int row = c >> 5, seg = c & 31;
        size_t go = (size_t)(s0 + row) * 512 + seg * 16;   // bytes
        uint32_t so = row * KST + seg * 16;
        cpa16(smb + ST_KHI(s) + so, (const char*)kh + go);
        cpa16(smb + ST_KLO(s) + so, (const char*)kl + go);
        cpa16(smb + ST_VH(s)  + so, (const char*)vh + go);
    }
}

__global__ __launch_bounds__(256) void flash_hmma() {
    extern __shared__ __align__(128) char sm[];
    uint32_t smb = s2u(sm);
    const int tid = threadIdx.x, lane = tid & 31, wid = tid >> 5;
    const int wm = wid >> 1, wn = wid & 1;
    const int bx = gridDim.x - 1 - blockIdx.x;    // heavy tiles first
    const int n = blockIdx.y, b = blockIdx.z;
    const int q0 = bx * 64;
    const size_t tb = (size_t)b * TT;

    const char* qh_g = (const char*)(g_Qsp + (size_t)(tb + q0) * DD + n * 256);
    const char* ql_g = (const char*)(g_Qsp + (size_t)TOK * DD
                                     + (size_t)(tb + q0) * DD + n * 256);
    const __nv_bfloat16* kh_g = g_Khi + tb * 256;
    const __nv_bfloat16* kl_g = g_Klo + tb * 256;
    const __half* vh_g = g_Vh + tb * 256;

    // ---- stage Q: hi -> stage1 K area (transient), lo -> persistent SQLO
#pragma unroll
    for (int i2 = 0; i2 < 8; ++i2) {
        int c = tid + i2 * 256;
        int row = c >> 5, seg = c & 31;
        cpa16(smb + ST_KHI(1) + row * KST + seg * 16, qh_g + (size_t)row * 4096 + seg * 16);
        cpa16(smb + SQLO + row * KST + seg * 16,      ql_g + (size_t)row * 4096 + seg * 16);
    }
    CP_COMMIT();
    CP_WAIT(0);
    __syncthreads();

    const uint32_t a_base = (uint32_t)((wm * 16 + (lane & 15)) * KST + (lane >> 4) * 16);
    uint32_t qh[16][4];
#pragma unroll
    for (int ks = 0; ks < 16; ++ks)
        LDSM4(qh[ks][0], qh[ks][1], qh[ks][2], qh[ks][3],
              smb + ST_KHI(1) + a_base + ks * 32);
    __syncthreads();   // Qhi consumed; stage1 free for K/V

    flash_load(smb, 0, 0, tid, kh_g, kl_g, vh_g);
    CP_COMMIT();

    float o[16][4];
#pragma unroll
    for (int nf = 0; nf < 16; ++nf)
#pragma unroll
        for (int r = 0; r < 4; ++r) o[nf][r] = 0.f;
    float m1 = -1e30f, m2 = -1e30f, l1 = 0.f, l2 = 0.f;

    const int grow1 = wm * 16 + (lane >> 2);
    const int grow2 = grow1 + 8;
    const int ccol = 2 * (lane & 3);
    float* rmaxs = (float*)(sm + SRED);
    float* rsums = (float*)(sm + SRED + 512);
    const uint32_t b_base = (uint32_t)((wn * 16 + ((lane >> 4) << 3) + (lane & 7)) * KST
                                       + ((lane >> 3) & 1) * 16);
    const uint32_t p_base = (uint32_t)((wm * 16 + (lane & 15)) * PST + (lane >> 4) * 16);
    const uint32_t v_base = (uint32_t)((lane & 15) * KST + wn * 256 + (lane >> 4) * 16);

    const int ntiles = 2 * bx + 2;
    for (int kt = 0; kt < ntiles; ++kt) {
        const int s = kt & 1;
        CP_WAIT(0);
        __syncthreads();
        if (kt + 1 < ntiles) {
            flash_load(smb, s ^ 1, (kt + 1) * BN, tid, kh_g, kl_g, vh_g);
            CP_COMMIT();
        }

        // ---- S = Q K^T (3x split)
        float sa[2][4];
#pragma unroll
        for (int nf = 0; nf < 2; ++nf)
#pragma unroll
            for (int r = 0; r < 4; ++r) sa[nf][r] = 0.f;
#pragma unroll
        for (int ks = 0; ks < 16; ++ks) {
            uint32_t ql[4];
            LDSM4(ql[0], ql[1], ql[2], ql[3], smb + SQLO + a_base + ks * 32);
            uint32_t bh0, bh1, bh2, bh3, bl0, bl1, bl2, bl3;
            LDSM4(bh0, bh1, bh2, bh3, smb + ST_KHI(s) + b_base + ks * 32);
            LDSM4(bl0, bl1, bl2, bl3, smb + ST_KLO(s) + b_base + ks * 32);
            MMA16816(sa[0], qh[ks], bh0, bh1);
            MMA16816(sa[1], qh[ks], bh2, bh3);
            MMA16816(sa[0], qh[ks], bl0, bl1);
            MMA16816(sa[1], qh[ks], bl2, bl3);
            MMA16816(sa[0], ql, bh0, bh1);
            MMA16816(sa[1], ql, bh2, bh3);
        }

        // ---- causal mask (only on last two tiles)
        const int s0 = kt * BN;
        if (kt >= 2 * bx) {
            const int qr1 = q0 + grow1, qr2 = q0 + grow2;
#pragma unroll
            for (int nf = 0; nf < 2; ++nf) {
                int c0 = s0 + wn * 16 + nf * 8 + ccol;
                if (c0     > qr1) sa[nf][0] = -1e30f;
                if (c0 + 1 > qr1) sa[nf][1] = -1e30f;
                if (c0     > qr2) sa[nf][2] = -1e30f;
                if (c0 + 1 > qr2) sa[nf][3] = -1e30f;
            }
        }

        // ---- online softmax
        float pm1 = fmaxf(fmaxf(sa[0][0], sa[0][1]), fmaxf(sa[1][0], sa[1][1]));
        float pm2 = fmaxf(fmaxf(sa[0][2], sa[0][3]), fmaxf(sa[1][2], sa[1][3]));
        pm1 = fmaxf(pm1, __shfl_xor_sync(0xffffffffu, pm1, 1));
        pm1 = fmaxf(pm1, __shfl_xor_sync(0xffffffffu, pm1, 2));
        pm2 = fmaxf(pm2, __shfl_xor_sync(0xffffffffu, pm2, 1));
        pm2 = fmaxf(pm2, __shfl_xor_sync(0xffffffffu, pm2, 2));
        if ((lane & 3) == 0) {
            rmaxs[wn * 64 + grow1] = pm1;
            rmaxs[wn * 64 + grow2] = pm2;
        }
        __syncthreads();
        float mn1 = fmaxf(m1, fmaxf(rmaxs[grow1], rmaxs[64 + grow1]));
        float mn2 = fmaxf(m2, fmaxf(rmaxs[grow2], rmaxs[64 + grow2]));
        float al1 = __expf(m1 - mn1), al2 = __expf(m2 - mn2);
        m1 = mn1; m2 = mn2;

        float ps1 = 0.f, ps2 = 0.f;
#pragma unroll
        for (int nf = 0; nf < 2; ++nf) {
            float e0 = __expf(sa[nf][0] - mn1), e1 = __expf(sa[nf][1] - mn1);
            float e2 = __expf(sa[nf][2] - mn2), e3 = __expf(sa[nf][3] - mn2);
            ps1 += e0 + e1; ps2 += e2 + e3;
            int colB = (wn * 16 + nf * 8 + ccol) * 2;
            *(__half2*)(sm + SPHI + grow1 * PST + colB) =
                __floats2half2_rn(e0, e1);
            *(__half2*)(sm + SPHI + grow2 * PST + colB) =
                __floats2half2_rn(e2, e3);
        }
        ps1 += __shfl_xor_sync(0xffffffffu, ps1, 1);
        ps1 += __shfl_xor_sync(0xffffffffu, ps1, 2);
        ps2 += __shfl_xor_sync(0xffffffffu, ps2, 1);
        ps2 += __shfl_xor_sync(0xffffffffu, ps2, 2);
        if ((lane & 3) == 0) {
            rsums[wn * 64 + grow1] = ps1;
            rsums[wn * 64 + grow2] = ps2;
        }
#pragma unroll
        for (int nf = 0; nf < 16; ++nf) {
            o[nf][0] *= al1; o[nf][1] *= al1;
            o[nf][2] *= al2; o[nf][3] *= al2;
        }
        __syncthreads();
        l1 = l1 * al1 + rsums[grow1] + rsums[64 + grow1];
        l2 = l2 * al2 + rsums[grow2] + rsums[64 + grow2];

        // ---- O += P V  (fp16 P)
#pragma unroll
        for (int ks = 0; ks < 2; ++ks) {
            uint32_t ph[4];
            LDSM4(ph[0], ph[1], ph[2], ph[3], smb + SPHI + p_base + ks * 32);
#pragma unroll
            for (int nb = 0; nb < 8; ++nb) {
                uint32_t v0, v1, v2, v3;
                LDSM4T(v0, v1, v2, v3,
                       smb + ST_VH(s) + v_base + ks * (16 * KST) + nb * 32);
                MMAF16(o[2 * nb],     ph, v0, v1);
                MMAF16(o[2 * nb + 1], ph, v2, v3);
            }
        }
    }

    // ---- epilogue: normalize, bf16 split straight into out-GEMM A buffers
    float i1 = 1.f / l1, i2 = 1.f / l2;
#pragma unroll
    for (int nf = 0; nf < 16; ++nf) {
        int col = n * 256 + wn * 128 + nf * 8 + ccol;
        size_t o1 = (tb + q0 + grow1) * (size_t)DD + col;
        size_t o2 = (tb + q0 + grow2) * (size_t)DD + col;
        float v0 = o[nf][0] * i1, v1 = o[nf][1] * i1;
        float v2 = o[nf][2] * i2, v3 = o[nf][3] * i2;
        __nv_bfloat16 h0 = __float2bfloat16(v0), h1 = __float2bfloat16(v1);
        __nv_bfloat16 h2 = __float2bfloat16(v2), h3 = __float2bfloat16(v3);
        *(__nv_bfloat162*)&g_Ahi[o1] = __halves2bfloat162(h0, h1);
        *(__nv_bfloat162*)&g_Ahi[o2] = __halves2bfloat162(h2, h3);
        *(__nv_bfloat162*)&g_Alo[o1] = __halves2bfloat162(
            __float2bfloat16(v0 - __bfloat162float(h0)),
            __float2bfloat16(v1 - __bfloat162float(h1)));
        *(__nv_bfloat162*)&g_Alo[o2] = __halves2bfloat162(
            __float2bfloat16(v2 - __bfloat162float(h2)),
            __float2bfloat16(v3 - __bfloat162float(h3)));
    }
}

// ===========================================================================
// launch — inputs: 0=x, 1=segment_pos, 2=attn_mask, 3=q_w, 4=kv_w, 5=out_w
// ===========================================================================
extern "C" void kernel_launch(void* const* d_in, const int* in_sizes, int n_in,
                              void* d_out, int out_size) {
    (void)in_sizes; (void)n_in; (void)out_size;
    const float* x   = (const float*)d_in[0];
    const float* qw  = (const float*)d_in[3];
    const float* kvw = (const float*)d_in[4];
    const float* ow  = (const float*)d_in[5];
    float* out = (float*)d_out;

    cudaFuncSetAttribute(gemm3x_kernel,
                         cudaFuncAttributeMaxDynamicSharedMemorySize, GSM_TOTAL);
    cudaFuncSetAttribute(flash_hmma,
                         cudaFuncAttributeMaxDynamicSharedMemorySize, FLASH_SMEM);

    rope_table<<<128, 256>>>();
    transpose_qkvw<<<dim3(HD / 32, DD / 32, 10), dim3(32, 8)>>>(qw, kvw);
    convert_split<<<(TOK * DD) / 4 / 256, 256>>>(x);

    // QKV projection + fused rope/scale/split epilogue
    gemm3x_kernel<<<dim3(NQKV / 128, TOK / 128), 256, GSM_TOTAL>>>(nullptr, 0);

    transpose_outw<<<dim3(DD / 32, DD / 32), dim3(32, 8)>>>(ow);

    // HMMA flash attention (writes enc bf16-split into g_Ahi/g_Alo)
    flash_hmma<<<dim3(TT / 64, NHEAD, BB), 256, FLASH_SMEM>>>();

    // Out projection
    gemm3x_kernel<<<dim3(DD / 128, TOK / 128), 256, GSM_TOTAL>>>(out, 1);
}